// round 13
// baseline (speedup 1.0000x reference)
#include <cuda_runtime.h>
#include <cuda_fp16.h>

// Problem constants
#define Hh   256
#define Gg   1024
#define Tt   50
#define Kk   3
#define FSn  6
#define Bb   4096
#define BTC  64            // batch rows per CLUSTER (2 CTAs share)
#define NTH  512
#define NWARP 16
#define NBLK (Bb/BTC*2)    // 128 CTAs = 64 clusters = one wave

#define KC0  17            // layer0 K = 272 = h(256) | x(4) | pad
#define KC1  32            // layer1 K = 512 = h0 | h1
#define A0S  280           // padded row stride (halves) -> conflict-free ldmatrix
#define A1S  520
#define CS2  132           // c-state row stride (floats, 128 units + pad)

// packed weight sizes (uint4 units): [kc][ntp(64)][lane(32)] * 16B
#define W0SZ (KC0*64*32)   // 34816
#define W1SZ (KC1*64*32)   // 65536

__device__ uint4  g_w0e[W0SZ];
__device__ uint4  g_w1e[W1SZ];
__device__ uint4  g_w0d[3*W0SZ];
__device__ uint4  g_w1d[3*W1SZ];
__device__ float2 g_bias2[8*512];     // 8 segments x 1024 floats, gate-packed col order
__device__ __half g_eA1[128*64*520];  // per-CTA encoder-final A1 snapshot (8.5MB)
__device__ float  g_ec0[128*64*128];  // per-CTA c0 snapshot (own units)
__device__ float  g_ec1[128*64*128];  // per-CTA c1 snapshot

struct Smem {
  __half A0[BTC*A0S];    // layer0 input rows: [h0(256) | x/inp(4) | pad]
  __half A1[BTC*A1S];    // layer1 input rows: [h0_new(256) | h1(256) | pad]
  __half xs[BTC*Tt*4];   // staged input sequence (f16)
  float  c0[BTC*CS2];    // own-unit cell states
  float  c1[BTC*CS2];
  float  inp[BTC*2];
  float  logit[BTC*Kk];
};

static __device__ __forceinline__ float sigm(float v) {
  return 1.0f / (1.0f + __expf(-v));
}
static __device__ __forceinline__ float tanhx(float v) {
  v = fminf(15.0f, fmaxf(-15.0f, v));
  float e = __expf(2.0f * v);
  return (e - 1.0f) / (e + 1.0f);
}

// ---- cluster helpers ----
static __device__ __forceinline__ unsigned ctarank() {
  unsigned r; asm("mov.u32 %0, %%cluster_ctarank;" : "=r"(r)); return r;
}
static __device__ __forceinline__ unsigned cvta_smem(const void* p) {
  return (unsigned)__cvta_generic_to_shared(p);
}
static __device__ __forceinline__ unsigned mapa_rank(unsigned saddr, unsigned rank) {
  unsigned r;
  asm("mapa.shared::cluster.u32 %0, %1, %2;" : "=r"(r) : "r"(saddr), "r"(rank));
  return r;
}
static __device__ __forceinline__ void st_cluster_u16(unsigned addr, __half v) {
  unsigned short u = __half_as_ushort(v);
  asm volatile("st.shared::cluster.b16 [%0], %1;" :: "r"(addr), "h"(u) : "memory");
}
static __device__ __forceinline__ void st_cluster_f32(unsigned addr, float v) {
  asm volatile("st.shared::cluster.b32 [%0], %1;" :: "r"(addr), "f"(v) : "memory");
}
static __device__ __forceinline__ void cluster_sync() {
  asm volatile("barrier.cluster.arrive.aligned;" ::: "memory");
  asm volatile("barrier.cluster.wait.aligned;" ::: "memory");
}

// ===================== converter: fp32 weights -> f16 B-fragment layout =====================
// Packed element (u32 = 2 f16) index: ((kc*64 + ntp)*32 + lane)*4 + q
//   nt = 2*ntp + (q>>1); n_col = nt*8 + (lane>>2)  (gate-packed: n = unit*4 + gate)
//   j_orig = (n_col&3)*256 + (n_col>>2);  k0 = kc*16 + (lane&3)*2 + (q&1)*8; elems k0, k0+1
__global__ void conv_kernel(
    const float* __restrict__ eWih0, const float* __restrict__ eWhh0,
    const float* __restrict__ ebih0, const float* __restrict__ ebhh0,
    const float* __restrict__ eWih1, const float* __restrict__ eWhh1,
    const float* __restrict__ ebih1, const float* __restrict__ ebhh1,
    const float* __restrict__ dWih0, const float* __restrict__ dWhh0,
    const float* __restrict__ dbih0, const float* __restrict__ dbhh0,
    const float* __restrict__ dWih1, const float* __restrict__ dWhh1,
    const float* __restrict__ dbih1, const float* __restrict__ dbhh1)
{
  const int WU0 = W0SZ*4;
  const int WU1 = W1SZ*4;
  const int WTOT = WU0 + WU1 + 3*WU0 + 3*WU1;
  int idx = blockIdx.x * 256 + threadIdx.x;
  if (idx < WTOT) {
    unsigned* dst; int kind; int mode = 0; int local = idx;
    if (local < WU0) { dst = (unsigned*)g_w0e; kind = 0; }
    else if ((local -= WU0) < WU1) { dst = (unsigned*)g_w1e; kind = 1; }
    else if ((local -= WU1) < 3*WU0) {
      mode = local / WU0; local -= mode*WU0;
      dst = (unsigned*)g_w0d + (size_t)mode*WU0; kind = 2;
    } else {
      local -= 3*WU0; mode = local / WU1; local -= mode*WU1;
      dst = (unsigned*)g_w1d + (size_t)mode*WU1; kind = 3;
    }
    int q = local & 3, lane = (local>>2)&31, ntp = (local>>7)&63, kc = local>>13;
    int nt = 2*ntp + (q>>1);
    int ncol = nt*8 + (lane>>2);
    int j = (ncol&3)*256 + (ncol>>2);
    int k0 = kc*16 + (lane&3)*2 + (q&1)*8;
    float v0, v1;
    if (kind == 0) {
      v0 = (k0   < 256) ? eWhh0[j*256 + k0]   : ((k0   < 260) ? eWih0[j*4 + k0-256]   : 0.f);
      v1 = (k0+1 < 256) ? eWhh0[j*256 + k0+1] : ((k0+1 < 260) ? eWih0[j*4 + k0+1-256] : 0.f);
    } else if (kind == 1) {
      v0 = (k0   < 256) ? eWih1[j*256 + k0]   : eWhh1[j*256 + k0-256];
      v1 = (k0+1 < 256) ? eWih1[j*256 + k0+1] : eWhh1[j*256 + k0+1-256];
    } else if (kind == 2) {
      int base = mode*1024 + j;
      v0 = (k0   < 256) ? dWhh0[base*256 + k0]   : ((k0   < 258) ? dWih0[base*2 + k0-256]   : 0.f);
      v1 = (k0+1 < 256) ? dWhh0[base*256 + k0+1] : ((k0+1 < 258) ? dWih0[base*2 + k0+1-256] : 0.f);
    } else {
      int base = mode*1024 + j;
      v0 = (k0   < 256) ? dWih1[base*256 + k0]   : dWhh1[base*256 + k0-256];
      v1 = (k0+1 < 256) ? dWih1[base*256 + k0+1] : dWhh1[base*256 + k0+1-256];
    }
    __half2 h = __floats2half2_rn(v0, v1);
    dst[local] = *(unsigned*)&h;
  } else if (idx < WTOT + 8192) {
    int n = idx - WTOT;
    int seg = n >> 10, col = n & 1023;
    int j = (col&3)*256 + (col>>2);
    float v;
    if      (seg == 0) v = ebih0[j] + ebhh0[j];
    else if (seg == 1) v = ebih1[j] + ebhh1[j];
    else if (seg < 5)  { int m = seg-2; v = dbih0[m*1024+j] + dbhh0[m*1024+j]; }
    else               { int m = seg-5; v = dbih1[m*1024+j] + dbhh1[m*1024+j]; }
    ((float*)g_bias2)[seg*1024 + col] = v;
  }
}

// ===================== MMA primitives =====================
static __device__ __forceinline__ void ldsm4(unsigned* a, unsigned addr) {
  asm volatile("ldmatrix.sync.aligned.m8n8.x4.shared.b16 {%0,%1,%2,%3}, [%4];"
               : "=r"(a[0]),"=r"(a[1]),"=r"(a[2]),"=r"(a[3]) : "r"(addr));
}
static __device__ __forceinline__ void mma16816(float* c, const unsigned* a,
                                                unsigned b0, unsigned b1) {
  asm volatile("mma.sync.aligned.m16n8k16.row.col.f32.f16.f16.f32 "
               "{%0,%1,%2,%3},{%4,%5,%6,%7},{%8,%9},{%0,%1,%2,%3};"
               : "+f"(c[0]),"+f"(c[1]),"+f"(c[2]),"+f"(c[3])
               : "r"(a[0]),"r"(a[1]),"r"(a[2]),"r"(a[3]),"r"(b0),"r"(b1));
}

// CTA rank owns global n-cols [rank*512, rank*512+512).
// Warp w owns ncols rank*512 + [w*32, w*32+32), all 64 batch rows.
// C[ntl(4)][mt(4)][4]  (64 f32 regs).
template<int KC>
static __device__ __forceinline__ void mma_block64(
    const __half* A, int As, const uint4* __restrict__ Wp,
    const float2* __restrict__ bias2, int rank, int w, int lane,
    float C[4][4][4])
{
  #pragma unroll
  for (int ntl = 0; ntl < 4; ntl++) {
    int ntg = rank*64 + w*4 + ntl;
    float2 bv = bias2[ntg*4 + (lane&3)];
    #pragma unroll
    for (int mt = 0; mt < 4; mt++) {
      C[ntl][mt][0] = bv.x; C[ntl][mt][1] = bv.y;
      C[ntl][mt][2] = bv.x; C[ntl][mt][3] = bv.y;
    }
  }
  int m = lane>>3, r = lane&7;
  unsigned abase = cvta_smem(A);
  unsigned aAddr[4];
  #pragma unroll
  for (int mt = 0; mt < 4; mt++)
    aAddr[mt] = abase + (unsigned)(((mt*16 + (m&1)*8 + r)*As + (m>>1)*8)*2);
  const uint4* p = Wp + (size_t)(rank*32 + w*2)*32 + lane;
  uint4 buf0 = p[0], buf1 = p[32];
  #pragma unroll 1
  for (int kc = 0; kc < KC; kc++) {
    unsigned a[4][4];
    #pragma unroll
    for (int mt = 0; mt < 4; mt++) { ldsm4(a[mt], aAddr[mt]); aAddr[mt] += 32; }
    const uint4* pn = p + (size_t)((kc+1 < KC) ? (kc+1) : 0) * 2048;
    uint4 b0 = buf0; buf0 = pn[0];
    #pragma unroll
    for (int mt = 0; mt < 4; mt++) {
      mma16816(C[0][mt], a[mt], b0.x, b0.y);
      mma16816(C[1][mt], a[mt], b0.z, b0.w);
    }
    uint4 b1 = buf1; buf1 = pn[32];
    #pragma unroll
    for (int mt = 0; mt < 4; mt++) {
      mma16816(C[2][mt], a[mt], b1.x, b1.y);
      mma16816(C[3][mt], a[mt], b1.z, b1.w);
    }
  }
}

// In-register cell update; writes h to own smem and peer CTA smem (DSMEM).
static __device__ __forceinline__ void cell_epi64(
    float C[4][4][4], int rank, int w, int lane,
    float* __restrict__ cS,
    __half* __restrict__ ownP, int ownStride, int ownOff, unsigned peerP,
    __half* __restrict__ ownS, unsigned peerS)
{
  const bool even = (lane & 1) == 0;
  const int rbase = (lane>>2) + (even ? 0 : 8);
  const int uoff = (lane&3) >> 1;
  #pragma unroll
  for (int ntl = 0; ntl < 4; ntl++) {
    int ug = (rank*64 + w*4 + ntl)*2 + uoff;   // global unit 0..255
    int ul = ug & 127;                          // local unit in own c-state
    #pragma unroll
    for (int mt = 0; mt < 4; mt++) {
      float x0 = __shfl_xor_sync(0xffffffffu, C[ntl][mt][0], 1);
      float x1 = __shfl_xor_sync(0xffffffffu, C[ntl][mt][1], 1);
      float x2 = __shfl_xor_sync(0xffffffffu, C[ntl][mt][2], 1);
      float x3 = __shfl_xor_sync(0xffffffffu, C[ntl][mt][3], 1);
      float gi, gf, gg, go;
      if (even) { gi = C[ntl][mt][0]; gf = C[ntl][mt][1]; gg = x0; go = x1; }
      else      { gi = x2; gf = x3; gg = C[ntl][mt][2]; go = C[ntl][mt][3]; }
      int row = mt*16 + rbase;
      float i_ = sigm(gi), f_ = sigm(gf), g_ = tanhx(gg), o_ = sigm(go);
      float cn = f_ * cS[row*CS2 + ul] + i_ * g_;
      cS[row*CS2 + ul] = cn;
      __half hv = __float2half(o_ * tanhx(cn));
      int offP = row*ownStride + ownOff + ug;
      ownP[offP] = hv;
      st_cluster_u16(peerP + (unsigned)(offP*2), hv);
      if (ownS) {
        int offS = row*A1S + ug;
        ownS[offS] = hv;
        st_cluster_u16(peerS + (unsigned)(offS*2), hv);
      }
    }
  }
}

// ===================== main kernel =====================
__global__ void __launch_bounds__(NTH, 1) __cluster_dims__(2, 1, 1)
mml_kernel(const float* __restrict__ x,
           const float* __restrict__ headW, const float* __restrict__ headB,
           const float* __restrict__ confW, const float* __restrict__ confB,
           float* __restrict__ out)
{
  extern __shared__ char raw[];
  Smem* s = reinterpret_cast<Smem*>(raw);
  const int tid = threadIdx.x, w = tid >> 5, lane = tid & 31;
  const int bid = blockIdx.x;
  const int rank = (int)ctarank();
  const int peer = rank ^ 1;
  const int crow0 = (bid >> 1) * BTC;

  const unsigned pA0  = mapa_rank(cvta_smem(s->A0),  peer);
  const unsigned pA1  = mapa_rank(cvta_smem(s->A1),  peer);
  const unsigned pInp = mapa_rank(cvta_smem(s->inp), peer);

  // ---- init: zero A0/A1/c, stage x as f16 ----
  {
    unsigned* a0u = (unsigned*)s->A0;
    unsigned* a1u = (unsigned*)s->A1;
    for (int i = tid; i < BTC*A0S/2; i += NTH) a0u[i] = 0u;
    for (int i = tid; i < BTC*A1S/2; i += NTH) a1u[i] = 0u;
    for (int i = tid; i < BTC*CS2; i += NTH) { s->c0[i] = 0.f; s->c1[i] = 0.f; }
    for (int i = tid; i < BTC*Tt*4; i += NTH) {
      int b = i / (Tt*4), o = i - b*(Tt*4);
      s->xs[i] = __float2half(x[(size_t)(crow0 + b)*(Tt*4) + o]);
    }
  }
  __syncthreads();
  cluster_sync();

  // ================= ENCODER =================
  for (int t = 0; t < Tt; t++) {
    if (tid < 256) {   // stage x_t -> A0 cols 256..259 (all 64 rows)
      int b = tid >> 2, d = tid & 3;
      s->A0[b*A0S + 256 + d] = s->xs[b*(Tt*4) + t*4 + d];
    }
    __syncthreads();
    {
      float C[4][4][4];
      mma_block64<KC0>(s->A0, A0S, g_w0e, g_bias2 + 0*512, rank, w, lane, C);
      cluster_sync();
      cell_epi64(C, rank, w, lane, s->c0, s->A0, A0S, 0, pA0, s->A1, pA1);
    }
    cluster_sync();
    {
      float C[4][4][4];
      mma_block64<KC1>(s->A1, A1S, g_w1e, g_bias2 + 1*512, rank, w, lane, C);
      cluster_sync();
      cell_epi64(C, rank, w, lane, s->c1, s->A1, A1S, 256, pA1, (__half*)nullptr, 0u);
    }
    // no trailing sync needed: next mma0 doesn't read A1; epi1 writes ordered by next cluster_sync
  }
  cluster_sync();   // all epi1 (incl. peer h1 into our A1) visible

  // ---- snapshot encoder-final state to global scratch ----
  {
    unsigned* du = (unsigned*)(g_eA1 + (size_t)bid*(BTC*A1S));
    const unsigned* a1u = (const unsigned*)s->A1;
    for (int i = tid; i < BTC*A1S/2; i += NTH) du[i] = a1u[i];
    float* d0 = g_ec0 + (size_t)bid*(BTC*128);
    float* d1 = g_ec1 + (size_t)bid*(BTC*128);
    for (int i = tid; i < BTC*128; i += NTH) {
      int row = i >> 7, ul = i & 127;
      d0[i] = s->c0[row*CS2 + ul];
      d1[i] = s->c1[row*CS2 + ul];
    }
  }

  // ---- confidence head (own 32 rows) ----
  for (int task = w; task < 32*Kk; task += NWARP) {
    int bl = rank*32 + task/Kk, k = task - (task/Kk)*Kk;
    float p = 0.f;
    for (int u = lane; u < Hh; u += 32)
      p += __half2float(s->A1[bl*A1S + 256 + u]) * confW[k*Hh + u];
    #pragma unroll
    for (int off = 16; off; off >>= 1) p += __shfl_down_sync(0xffffffffu, p, off);
    if (lane == 0) s->logit[bl*Kk + k] = p + confB[k];
  }
  __syncthreads();
  if (tid < 32) {
    int bl = rank*32 + tid;
    int r = crow0 + bl;
    float l0 = s->logit[bl*Kk], l1 = s->logit[bl*Kk+1], l2 = s->logit[bl*Kk+2];
    float m = fmaxf(l0, fmaxf(l1, l2));
    float e0 = __expf(l0-m), e1 = __expf(l1-m), e2 = __expf(l2-m);
    float inv = 1.f / (e0 + e1 + e2);
    float* cp = out + (size_t)Bb*Kk*FSn*2 + (size_t)r*Kk;
    cp[0] = e0*inv; cp[1] = e1*inv; cp[2] = e2*inv;
  }

  // ================= DECODER =================
  for (int km = 0; km < Kk; km++) {
    __syncthreads();
    {  // restore encoder-final state from global scratch (own data only)
      unsigned* a1u = (unsigned*)s->A1;
      unsigned* a0u = (unsigned*)s->A0;
      const unsigned* eu = (const unsigned*)(g_eA1 + (size_t)bid*(BTC*A1S));
      for (int i = tid; i < BTC*A1S/2; i += NTH) a1u[i] = eu[i];
      for (int i = tid; i < BTC*128; i += NTH) {
        int b = i >> 7, c = i & 127;
        a0u[b*(A0S/2) + c] = eu[b*(A1S/2) + c];   // h0 cols 0..255
      }
      const float* d0 = g_ec0 + (size_t)bid*(BTC*128);
      const float* d1 = g_ec1 + (size_t)bid*(BTC*128);
      for (int i = tid; i < BTC*128; i += NTH) {
        int row = i >> 7, ul = i & 127;
        s->c0[row*CS2 + ul] = d0[i];
        s->c1[row*CS2 + ul] = d1[i];
      }
      if (tid < BTC*2) {
        int b = tid >> 1, d = tid & 1;
        s->inp[tid] = __half2float(s->xs[b*(Tt*4) + (Tt-1)*4 + d]);
      }
    }
    __syncthreads();

    const uint4* w0p = g_w0d + (size_t)km*W0SZ;
    const uint4* w1p = g_w1d + (size_t)km*W1SZ;
    const float2* b0p = g_bias2 + (2+km)*512;
    const float2* b1p = g_bias2 + (5+km)*512;

    for (int t = 0; t < FSn; t++) {
      if (tid < 128) {  // stage feedback -> A0 cols 256,257 (258,259 zero-weighted)
        int b = tid >> 1, d = tid & 1;
        s->A0[b*A0S + 256 + d] = __float2half(s->inp[b*2 + d]);
      }
      __syncthreads();
      {
        float C[4][4][4];
        mma_block64<KC0>(s->A0, A0S, w0p, b0p, rank, w, lane, C);
        cluster_sync();
        cell_epi64(C, rank, w, lane, s->c0, s->A0, A0S, 0, pA0, s->A1, pA1);
      }
      cluster_sync();
      {
        float C[4][4][4];
        mma_block64<KC1>(s->A1, A1S, w1p, b1p, rank, w, lane, C);
        cluster_sync();
        cell_epi64(C, rank, w, lane, s->c1, s->A1, A1S, 256, pA1, (__half*)nullptr, 0u);
      }
      cluster_sync();   // head reads full h1 (incl. peer-written half)
      // head: own 32 rows; feed back inp to both CTAs
      for (int task = w; task < 64; task += NWARP) {
        int bl = rank*32 + (task >> 1), d = task & 1;
        float p = 0.f;
        const float* hw = headW + (size_t)(km*2 + d)*Hh;
        for (int u = lane; u < Hh; u += 32)
          p += __half2float(s->A1[bl*A1S + 256 + u]) * hw[u];
        #pragma unroll
        for (int off = 16; off; off >>= 1) p += __shfl_down_sync(0xffffffffu, p, off);
        if (lane == 0) {
          p += headB[km*2 + d];
          s->inp[bl*2 + d] = p;
          st_cluster_f32(pInp + (unsigned)((bl*2 + d)*4), p);
          int r = crow0 + bl;
          out[((((size_t)r*Kk + km)*FSn + t)*2) + d] = p;
        }
      }
      cluster_sync();   // inp exchange visible before next staging
    }
  }
}

extern "C" void kernel_launch(void* const* d_in, const int* in_sizes, int n_in,
                              void* d_out, int out_size) {
  (void)in_sizes; (void)n_in; (void)out_size;
  const float* x     = (const float*)d_in[0];
  const float* eWih0 = (const float*)d_in[1];
  const float* eWhh0 = (const float*)d_in[2];
  const float* ebih0 = (const float*)d_in[3];
  const float* ebhh0 = (const float*)d_in[4];
  const float* eWih1 = (const float*)d_in[5];
  const float* eWhh1 = (const float*)d_in[6];
  const float* ebih1 = (const float*)d_in[7];
  const float* ebhh1 = (const float*)d_in[8];
  const float* dWih0 = (const float*)d_in[9];
  const float* dWhh0 = (const float*)d_in[10];
  const float* dbih0 = (const float*)d_in[11];
  const float* dbhh0 = (const float*)d_in[12];
  const float* dWih1 = (const float*)d_in[13];
  const float* dWhh1 = (const float*)d_in[14];
  const float* dbih1 = (const float*)d_in[15];
  const float* dbhh1 = (const float*)d_in[16];
  const float* headW = (const float*)d_in[17];
  const float* headB = (const float*)d_in[18];
  const float* confW = (const float*)d_in[19];
  const float* confB = (const float*)d_in[20];
  float* out = (float*)d_out;

  // 1) pack weights/biases into fragment layout (f16)
  const int WU0 = W0SZ*4, WU1 = W1SZ*4;
  const int total = WU0 + WU1 + 3*WU0 + 3*WU1 + 8192;
  conv_kernel<<<(total + 255)/256, 256>>>(
      eWih0, eWhh0, ebih0, ebhh0, eWih1, eWhh1, ebih1, ebhh1,
      dWih0, dWhh0, dbih0, dbhh0, dWih1, dWhh1, dbih1, dbhh1);

  // 2) persistent clustered LSTM kernel
  const int smem_bytes = (int)sizeof(Smem);
  cudaFuncSetAttribute(mml_kernel, cudaFuncAttributeMaxDynamicSharedMemorySize,
                       smem_bytes);
  mml_kernel<<<NBLK, NTH, smem_bytes>>>(x, headW, headB, confW, confB, out);
}